// round 5
// baseline (speedup 1.0000x reference)
#include <cuda_runtime.h>

// Fused avgpool(5x5,s2) + Linear(36->1): out[b,c] = dot(x[b,c,:,:], G) + bias,
// G[h*16+w] = (1/25)*sum_{pool windows (i,j) covering (h,w)} W[i*6+j].
//
// Persistent grid-stride kernel: one wave of blocks, each warp loops over
// 4-row tiles. Lane map: rsub = lane>>3 (row 0..3), chunk = lane&7
// (32-float segment). Per iteration each lane does 8 independent __ldcs
// float4 loads, a 32-FMA dot vs a register-resident filter, and a 3-level
// shfl_xor reduce shared by all 4 rows.

#define NROWS 131072          // B*C
#define NTILES (NROWS / 4)    // 4 rows per warp-tile = 32768 warp-tiles
// warp-tiles consumed 8 at a time per block (8 warps)

__global__ void __launch_bounds__(256)
pool_linear_kernel(const float4* __restrict__ x,
                   const float* __restrict__ W,
                   const float* __restrict__ bias,
                   float* __restrict__ out) {
    __shared__ float gsh[256];
    __shared__ float bsh;

    int tid   = threadIdx.x;
    int lane  = tid & 31;
    int warp  = tid >> 5;            // 0..7
    int chunk = lane & 7;            // 32-float segment within row
    int rsub  = lane >> 3;           // row within 4-row tile

    // ---- Build folded filter in shared once per block
    {
        int h = tid >> 4;
        int w = tid & 15;
        float s = 0.0f;
        #pragma unroll
        for (int i = 0; i < 6; i++) {
            int top = i * 2;
            bool hin = (h >= top) && (h <= top + 4);
            #pragma unroll
            for (int j = 0; j < 6; j++) {
                int left = j * 2;
                if (hin && (w >= left) && (w <= left + 4)) s += W[i * 6 + j];
            }
        }
        gsh[tid] = s * 0.04f;        // 1/25
        if (tid == 0) bsh = bias[0];
    }
    __syncthreads();

    // ---- Filter taps for this lane into registers (8 float4)
    const float4* gv = reinterpret_cast<const float4*>(gsh);
    float4 g[8];
    #pragma unroll
    for (int k = 0; k < 8; k++)
        g[k] = gv[k * 8 + chunk];
    float bv = bsh;

    // ---- Persistent loop over warp-tiles (4 rows each)
    int wstride = gridDim.x * 8;                 // warp-tiles per grid step
    for (int wt = blockIdx.x * 8 + warp; wt < NTILES; wt += wstride) {
        int row_base = wt * 4;
        const float4* p = x + (size_t)(row_base + rsub) * 64 + chunk;

        // 8 independent streaming loads (evict-first)
        float4 a[8];
        #pragma unroll
        for (int k = 0; k < 8; k++)
            a[k] = __ldcs(p + k * 8);

        float s0 = 0.0f, s1 = 0.0f;
        #pragma unroll
        for (int k = 0; k < 8; k += 2) {
            s0 += a[k].x * g[k].x + a[k].y * g[k].y
                + a[k].z * g[k].z + a[k].w * g[k].w;
            s1 += a[k+1].x * g[k+1].x + a[k+1].y * g[k+1].y
                + a[k+1].z * g[k+1].z + a[k+1].w * g[k+1].w;
        }
        float s = s0 + s1;

        // reduce within 8-lane groups (covers all 4 rows at once)
        s += __shfl_xor_sync(0xffffffffu, s, 1);
        s += __shfl_xor_sync(0xffffffffu, s, 2);
        s += __shfl_xor_sync(0xffffffffu, s, 4);

        if (chunk == 0)
            out[row_base + rsub] = s + bv;
    }
}

extern "C" void kernel_launch(void* const* d_in, const int* in_sizes, int n_in,
                              void* d_out, int out_size) {
    const float* x = (const float*)d_in[0];   // [256, 512, 16, 16]
    const float* W = (const float*)d_in[1];   // [1, 36]
    const float* b = (const float*)d_in[2];   // [1]
    float* out = (float*)d_out;               // [256*512]

    int blocks = 592;                         // ~one wave on 148 SMs @ occ 4
    pool_linear_kernel<<<blocks, 256>>>(
        reinterpret_cast<const float4*>(x), W, b, out);
}